// round 12
// baseline (speedup 1.0000x reference)
#include <cuda_runtime.h>
#include <cuda_fp16.h>
#include <math.h>
#include <stdint.h>
#include <string.h>

// Problem constants
#define BB   2
#define SS   2048
#define DD   1024
#define HH   16
#define DH   64
#define FF   4096
#define NTOK (BB*SS)          // 4096 rows
#define D3   (3*DD)           // 3072

// ---------------------------------------------------------------------------
// Scratch (static device globals)
// ---------------------------------------------------------------------------
__device__ float  g_proj[NTOK * DD];
__device__ float  g_hbuf[NTOK * DD];
__device__ float  g_m2  [NTOK * DD];
__device__ __half g_xh   [NTOK * DD];
__device__ __half g_wqkvh[D3 * DD];
__device__ __half g_woh  [DD * DD];
__device__ __half g_w1h  [2 * FF * DD];
__device__ __half g_w2h  [DD * FF];
__device__ __half g_attnh[NTOK * DD];
__device__ __half g_hh   [NTOK * DD];
__device__ __half g_mh   [NTOK * FF];
__device__ __half g_qh   [NTOK * DD];
__device__ __half g_kh   [NTOK * DD];
__device__ __half g_vth  [BB * HH * DH * SS];

// ---------------------------------------------------------------------------
// helpers
// ---------------------------------------------------------------------------
__device__ __forceinline__ uint32_t h2_as_u32(__half2 h) {
    uint32_t u; memcpy(&u, &h, 4); return u;
}

__device__ __forceinline__ void mma_f16(
    float& d0, float& d1, float& d2, float& d3,
    uint32_t a0, uint32_t a1, uint32_t a2, uint32_t a3,
    uint32_t b0, uint32_t b1)
{
    asm volatile(
        "mma.sync.aligned.m16n8k16.row.col.f32.f16.f16.f32 "
        "{%0,%1,%2,%3}, {%4,%5,%6,%7}, {%8,%9}, {%0,%1,%2,%3};"
        : "+f"(d0), "+f"(d1), "+f"(d2), "+f"(d3)
        : "r"(a0), "r"(a1), "r"(a2), "r"(a3), "r"(b0), "r"(b1));
}

__device__ __forceinline__ void ldsm_x4(
    uint32_t& r0, uint32_t& r1, uint32_t& r2, uint32_t& r3, uint32_t addr)
{
    asm volatile(
        "ldmatrix.sync.aligned.m8n8.x4.shared.b16 {%0,%1,%2,%3}, [%4];"
        : "=r"(r0), "=r"(r1), "=r"(r2), "=r"(r3) : "r"(addr));
}

__device__ __forceinline__ uint32_t smem_u32(const void* p) {
    uint32_t a;
    asm("{ .reg .u64 t; cvta.to.shared.u64 t, %1; cvt.u32.u64 %0, t; }"
        : "=r"(a) : "l"(p));
    return a;
}

__device__ __forceinline__ void cp_async16(uint32_t s, const void* g) {
    asm volatile("cp.async.cg.shared.global [%0], [%1], 16;\n"
                 :: "r"(s), "l"(g));
}
__device__ __forceinline__ void cp_commit() {
    asm volatile("cp.async.commit_group;\n");
}
template<int N> __device__ __forceinline__ void cp_wait() {
    asm volatile("cp.async.wait_group %0;\n" :: "n"(N));
}

__device__ __forceinline__ void store2(float* C, size_t idx, float a, float b) {
    *(float2*)&C[idx] = make_float2(a, b);
}
__device__ __forceinline__ void store2(__half* C, size_t idx, float a, float b) {
    *(__half2*)&C[idx] = __floats2half2_rn(a, b);
}

// ---------------------------------------------------------------------------
// fp32 -> fp16 copy
// ---------------------------------------------------------------------------
__global__ void __launch_bounds__(256) h_copy_kernel(
    const float* __restrict__ s, __half* __restrict__ d, int n4)
{
    int i = blockIdx.x * blockDim.x + threadIdx.x;
    if (i < n4) {
        float4 v = ((const float4*)s)[i];
        ((__half2*)d)[2 * i]     = __floats2half2_rn(v.x, v.y);
        ((__half2*)d)[2 * i + 1] = __floats2half2_rn(v.z, v.w);
    }
}

// ---------------------------------------------------------------------------
// Shared GEMM mainloop pieces (CTA 128x128, BK=32, 8 warps, ldmatrix frags)
// ---------------------------------------------------------------------------
#define HSTR    40
#define STAGE_H (2 * 128 * HSTR)
#define GH_SMEM (3 * STAGE_H * 2)          // 61440 B

// ---------------------------------------------------------------------------
// FP16 tensor-core GEMM: C = A @ W^T + bias
// ---------------------------------------------------------------------------
template<typename OutT>
__global__ void __launch_bounds__(256) gemm_f16_nt_bias(
    const __half* __restrict__ A, const __half* __restrict__ W,
    const float* __restrict__ bias, OutT* __restrict__ C,
    int M, int N, int K)
{
    extern __shared__ __align__(16) char smc[];
    __half* smh = (__half*)smc;

    const int tid  = threadIdx.x;
    const int m0   = blockIdx.y * 128;
    const int n0   = blockIdx.x * 128;
    const int warp = tid >> 5;
    const int lane = tid & 31;
    const int g    = lane >> 2;
    const int t    = lane & 3;
    const int wm   = (warp >> 2) * 64;
    const int wn   = (warp & 3) * 32;

    const int lrow = tid >> 1;
    const int lc   = (tid & 1) * 16;
    const __half* Ag = A + (size_t)(m0 + lrow) * K + lc;
    const __half* Wg = W + (size_t)(n0 + lrow) * K + lc;
    const uint32_t smb = smem_u32(smh);

    const int NK = K >> 5;

    auto issue = [&](int kt) {
        const int buf = kt % 3;
        uint32_t dA = smb + (uint32_t)(buf * STAGE_H + lrow * HSTR + lc) * 2;
        uint32_t dB = dA + 128 * HSTR * 2;
        const __half* a = Ag + (size_t)kt * 32;
        const __half* w = Wg + (size_t)kt * 32;
        cp_async16(dA,      a);
        cp_async16(dA + 16, a + 8);
        cp_async16(dB,      w);
        cp_async16(dB + 16, w + 8);
        cp_commit();
    };

    const uint32_t aRow = (uint32_t)(lane & 15);
    const uint32_t aKh  = (uint32_t)((lane >> 4) << 3);
    const uint32_t bRow = (uint32_t)((lane & 7) + ((lane >> 4) << 3));
    const uint32_t bKh  = (uint32_t)(lane & 8);

    uint32_t af0[4][4], bf0[4][2], af1[4][4], bf1[4][2];

    auto ldfrag = [&](int buf, int ks, uint32_t af[4][4], uint32_t bf[4][2]) {
        const uint32_t aBase = smb + (uint32_t)(buf * STAGE_H) * 2;
        const uint32_t bBase = aBase + 128 * HSTR * 2;
        const uint32_t kh = (uint32_t)(ks * 16);
#pragma unroll
        for (int i = 0; i < 4; i++) {
            uint32_t addr = aBase + (((uint32_t)(wm + i * 16) + aRow) * HSTR + kh + aKh) * 2;
            ldsm_x4(af[i][0], af[i][1], af[i][2], af[i][3], addr);
        }
#pragma unroll
        for (int jp = 0; jp < 2; jp++) {
            uint32_t addr = bBase + (((uint32_t)(wn + jp * 16) + bRow) * HSTR + kh + bKh) * 2;
            ldsm_x4(bf[2 * jp][0], bf[2 * jp][1], bf[2 * jp + 1][0], bf[2 * jp + 1][1], addr);
        }
    };

    float acc[4][4][4];
#pragma unroll
    for (int i = 0; i < 4; i++)
#pragma unroll
        for (int j = 0; j < 4; j++)
#pragma unroll
            for (int r = 0; r < 4; r++) acc[i][j][r] = 0.f;

    auto mma16 = [&](uint32_t af[4][4], uint32_t bf[4][2]) {
#pragma unroll
        for (int j = 0; j < 4; j++)
#pragma unroll
            for (int i = 0; i < 4; i++)
                mma_f16(acc[i][j][0], acc[i][j][1], acc[i][j][2], acc[i][j][3],
                        af[i][0], af[i][1], af[i][2], af[i][3],
                        bf[j][0], bf[j][1]);
    };

    issue(0);
    issue(1);
    cp_wait<1>();
    __syncthreads();
    ldfrag(0, 0, af0, bf0);

    for (int kt = 0; kt < NK; kt++) {
        const int buf = kt % 3;
        ldfrag(buf, 1, af1, bf1);
        mma16(af0, bf0);
        const bool more2 = (kt + 2) < NK;
        if (more2) issue(kt + 2);
        mma16(af1, bf1);
        if (kt + 1 < NK) {
            if (more2) cp_wait<1>();
            else       cp_wait<0>();
            __syncthreads();
            ldfrag((kt + 1) % 3, 0, af0, bf0);
        }
    }

#pragma unroll
    for (int i = 0; i < 4; i++) {
        const int r0 = m0 + wm + i * 16 + g;
        const int r1 = r0 + 8;
#pragma unroll
        for (int j = 0; j < 4; j++) {
            const int col = n0 + wn + j * 8 + 2 * t;
            float2 bv = *(const float2*)&bias[col];
            store2(C, (size_t)r0 * N + col, acc[i][j][0] + bv.x, acc[i][j][1] + bv.y);
            store2(C, (size_t)r1 * N + col, acc[i][j][2] + bv.x, acc[i][j][3] + bv.y);
        }
    }
}

// ---------------------------------------------------------------------------
// QKV GEMM with fused RoPE epilogue.
// N = 3072 fixed; region = q/k/v by n0. Epilogue stages acc+bias to smem as
// fp16 (same rounding point as the old qkvh buffer), applies RoPE (q,k) or
// the V transpose, writing qh/kh/vth directly.
// ---------------------------------------------------------------------------
#define QR_STR   136                        // halves per staging row
#define QR_SMEM  (GH_SMEM)                  // staging (34816 B) < GH_SMEM

__global__ void __launch_bounds__(256) gemm_qkv_rope(
    const __half* __restrict__ A, const __half* __restrict__ W,
    const float* __restrict__ bias, const int* __restrict__ p,
    const float* __restrict__ freqs,
    __half* __restrict__ qh, __half* __restrict__ kh,
    __half* __restrict__ vth, int K)
{
    extern __shared__ __align__(16) char smc[];
    __half* smh = (__half*)smc;

    const int tid  = threadIdx.x;
    const int m0   = blockIdx.y * 128;
    const int n0   = blockIdx.x * 128;
    const int warp = tid >> 5;
    const int lane = tid & 31;
    const int g    = lane >> 2;
    const int t    = lane & 3;
    const int wm   = (warp >> 2) * 64;
    const int wn   = (warp & 3) * 32;

    const int lrow = tid >> 1;
    const int lc   = (tid & 1) * 16;
    const __half* Ag = A + (size_t)(m0 + lrow) * K + lc;
    const __half* Wg = W + (size_t)(n0 + lrow) * K + lc;
    const uint32_t smb = smem_u32(smh);

    const int NK = K >> 5;

    auto issue = [&](int kt) {
        const int buf = kt % 3;
        uint32_t dA = smb + (uint32_t)(buf * STAGE_H + lrow * HSTR + lc) * 2;
        uint32_t dB = dA + 128 * HSTR * 2;
        const __half* a = Ag + (size_t)kt * 32;
        const __half* w = Wg + (size_t)kt * 32;
        cp_async16(dA,      a);
        cp_async16(dA + 16, a + 8);
        cp_async16(dB,      w);
        cp_async16(dB + 16, w + 8);
        cp_commit();
    };

    const uint32_t aRow = (uint32_t)(lane & 15);
    const uint32_t aKh  = (uint32_t)((lane >> 4) << 3);
    const uint32_t bRow = (uint32_t)((lane & 7) + ((lane >> 4) << 3));
    const uint32_t bKh  = (uint32_t)(lane & 8);

    uint32_t af0[4][4], bf0[4][2], af1[4][4], bf1[4][2];

    auto ldfrag = [&](int buf, int ks, uint32_t af[4][4], uint32_t bf[4][2]) {
        const uint32_t aBase = smb + (uint32_t)(buf * STAGE_H) * 2;
        const uint32_t bBase = aBase + 128 * HSTR * 2;
        const uint32_t kh = (uint32_t)(ks * 16);
#pragma unroll
        for (int i = 0; i < 4; i++) {
            uint32_t addr = aBase + (((uint32_t)(wm + i * 16) + aRow) * HSTR + kh + aKh) * 2;
            ldsm_x4(af[i][0], af[i][1], af[i][2], af[i][3], addr);
        }
#pragma unroll
        for (int jp = 0; jp < 2; jp++) {
            uint32_t addr = bBase + (((uint32_t)(wn + jp * 16) + bRow) * HSTR + kh + bKh) * 2;
            ldsm_x4(bf[2 * jp][0], bf[2 * jp][1], bf[2 * jp + 1][0], bf[2 * jp + 1][1], addr);
        }
    };

    float acc[4][4][4];
#pragma unroll
    for (int i = 0; i < 4; i++)
#pragma unroll
        for (int j = 0; j < 4; j++)
#pragma unroll
            for (int r = 0; r < 4; r++) acc[i][j][r] = 0.f;

    auto mma16 = [&](uint32_t af[4][4], uint32_t bf[4][2]) {
#pragma unroll
        for (int j = 0; j < 4; j++)
#pragma unroll
            for (int i = 0; i < 4; i++)
                mma_f16(acc[i][j][0], acc[i][j][1], acc[i][j][2], acc[i][j][3],
                        af[i][0], af[i][1], af[i][2], af[i][3],
                        bf[j][0], bf[j][1]);
    };

    issue(0);
    issue(1);
    cp_wait<1>();
    __syncthreads();
    ldfrag(0, 0, af0, bf0);

    for (int kt = 0; kt < NK; kt++) {
        const int buf = kt % 3;
        ldfrag(buf, 1, af1, bf1);
        mma16(af0, bf0);
        const bool more2 = (kt + 2) < NK;
        if (more2) issue(kt + 2);
        mma16(af1, bf1);
        if (kt + 1 < NK) {
            if (more2) cp_wait<1>();
            else       cp_wait<0>();
            __syncthreads();
            ldfrag((kt + 1) % 3, 0, af0, bf0);
        }
    }

    // ---- stage acc+bias as fp16 into smem ----
    __syncthreads();                     // pipeline smem is dead now
    __half* Hs = smh;                    // 128 x QR_STR halves
#pragma unroll
    for (int i = 0; i < 4; i++) {
        const int r0 = wm + i * 16 + g;
        const int r1 = r0 + 8;
#pragma unroll
        for (int j = 0; j < 4; j++) {
            const int col = wn + j * 8 + 2 * t;
            float2 bv = *(const float2*)&bias[n0 + col];
            *(__half2*)&Hs[r0 * QR_STR + col] =
                __floats2half2_rn(acc[i][j][0] + bv.x, acc[i][j][1] + bv.y);
            *(__half2*)&Hs[r1 * QR_STR + col] =
                __floats2half2_rn(acc[i][j][2] + bv.x, acc[i][j][3] + bv.y);
        }
    }
    __syncthreads();

    const int region = n0 >> 10;         // 0=q, 1=k, 2=v
    const int cb = n0 & 1023;

    if (region < 2) {
        __half* dst_base = (region == 0) ? qh : kh;
        const float qs = (region == 0) ? 0.125f : 1.0f;
        for (int idx = tid; idx < 128 * 64; idx += 256) {
            const int r  = idx >> 6;
            const int c2 = (idx & 63) * 2;
            const int dh = c2 & 63;
            const int off = (dh < 32) ? 32 : -32;
            const float pos = (float)p[m0 + r];

            float2 v = __half22float2(*(const __half2*)&Hs[r * QR_STR + c2]);
            float2 o = __half22float2(*(const __half2*)&Hs[r * QR_STR + c2 + off]);
            float s0, c0, s1, c1;
            __sincosf(pos * freqs[dh],     &s0, &c0);
            __sincosf(pos * freqs[dh + 1], &s1, &c1);
            float r0f = (v.x * c0 + o.x * s0) * qs;
            float r1f = (v.y * c1 + o.y * s1) * qs;
            *(__half2*)&dst_base[(size_t)(m0 + r) * DD + cb + c2] =
                __floats2half2_rn(r0f, r1f);
        }
    } else {
        for (int idx = tid; idx < 128 * 64; idx += 256) {
            const int r   = idx >> 6;
            const int c2  = (idx & 63) * 2;
            const int col = cb + c2;
            const int h   = col >> 6;
            const int d0  = col & 63;
            const int row = m0 + r;
            const int b   = row / SS;
            const int s   = row - b * SS;
            __half2 v = *(const __half2*)&Hs[r * QR_STR + c2];
            __half* dst = vth + ((size_t)(b * HH + h) * DH + d0) * SS + s;
            dst[0]  = __low2half(v);
            dst[SS] = __high2half(v);
        }
    }
}

// ---------------------------------------------------------------------------
// W1 GEMM fused with GELU*gate (ldmatrix frags; unchanged from R11)
// ---------------------------------------------------------------------------
#define CS_STR   132
#define W1_SMEM  (128 * CS_STR * 4)

__global__ void __launch_bounds__(256) gemm_w1_gelu(
    const __half* __restrict__ A, const __half* __restrict__ W,
    const float* __restrict__ bias, __half* __restrict__ Mout,
    int M, int K)
{
    extern __shared__ __align__(16) char smc[];
    __half* smh = (__half*)smc;

    const int tid  = threadIdx.x;
    const int m0   = blockIdx.y * 128;
    const int n0m  = blockIdx.x * 64;
    const int warp = tid >> 5;
    const int lane = tid & 31;
    const int g    = lane >> 2;
    const int t    = lane & 3;
    const int wm   = (warp >> 2) * 64;
    const int wn   = (warp & 3) * 32;

    const int lrow = tid >> 1;
    const int lc   = (tid & 1) * 16;
    const int wrow = (lrow < 64) ? (n0m + lrow) : (FF + n0m + lrow - 64);
    const __half* Ag = A + (size_t)(m0 + lrow) * K + lc;
    const __half* Wg = W + (size_t)wrow * K + lc;
    const uint32_t smb = smem_u32(smh);

    const int NK = K >> 5;

    auto issue = [&](int kt) {
        const int buf = kt % 3;
        uint32_t dA = smb + (uint32_t)(buf * STAGE_H + lrow * HSTR + lc) * 2;
        uint32_t dB = dA + 128 * HSTR * 2;
        const __half* a = Ag + (size_t)kt * 32;
        const __half* w = Wg + (size_t)kt * 32;
        cp_async16(dA,      a);
        cp_async16(dA + 16, a + 8);
        cp_async16(dB,      w);
        cp_async16(dB + 16, w + 8);
        cp_commit();
    };

    const uint32_t aRow = (uint32_t)(lane & 15);
    const uint32_t aKh  = (uint32_t)((lane >> 4) << 3);
    const uint32_t bRow = (uint32_t)((lane & 7) + ((lane >> 4) << 3));
    const uint32_t bKh  = (uint32_t)(lane & 8);

    uint32_t af0[4][4], bf0[4][2], af1[4][4], bf1[4][2];

    auto ldfrag = [&](int buf, int ks, uint32_t af[4][4], uint32_t bf[4][2]) {
        const uint32_t aBase = smb + (uint32_t)(buf * STAGE_H) * 2;
        const uint32_t bBase = aBase + 128 * HSTR * 2;
        const uint32_t kh = (uint32_t)(ks * 16);
#pragma unroll
        for (int i = 0; i < 4; i++) {
            uint32_t addr = aBase + (((uint32_t)(wm + i * 16) + aRow) * HSTR + kh + aKh) * 2;
            ldsm_x4(af[i][0], af[i][1], af[i][2], af[i][3], addr);
        }
#pragma unroll
        for (int jp = 0; jp < 2; jp++) {
            uint32_t addr = bBase + (((uint32_t)(wn + jp * 16) + bRow) * HSTR + kh + bKh) * 2;
            ldsm_x4(bf[2 * jp][0], bf[2 * jp][1], bf[2 * jp + 1][0], bf[2 * jp + 1][1], addr);
        }
    };

    float acc[4][4][4];
#pragma unroll
    for (int i = 0; i < 4; i++)
#pragma unroll
        for (int j = 0; j < 4; j++)
#pragma unroll
            for (int r = 0; r < 4; r++) acc[i][j][r] = 0.f;

    auto mma16 = [&](uint32_t af[4][4], uint32_t bf[4][2]) {
#pragma unroll
        for (int j = 0; j < 4; j++)
#pragma unroll
            for (int i = 0; i < 4; i++)
                mma_f16(acc[i][j][0], acc[i][j][1], acc[i][j][2], acc[i][j][3],
                        af[i][0], af[i][1], af[i][2], af[i][3],
                        bf[j][0], bf[j][1]);
    };

    issue(0);
    issue(1);
    cp_wait<1>();
    __syncthreads();
    ldfrag(0, 0, af0, bf0);

    for (int kt = 0; kt < NK; kt++) {
        const int buf = kt % 3;
        ldfrag(buf, 1, af1, bf1);
        mma16(af0, bf0);
        const bool more2 = (kt + 2) < NK;
        if (more2) issue(kt + 2);
        mma16(af1, bf1);
        if (kt + 1 < NK) {
            if (more2) cp_wait<1>();
            else       cp_wait<0>();
            __syncthreads();
            ldfrag((kt + 1) % 3, 0, af0, bf0);
        }
    }

    __syncthreads();
    float* Cs = (float*)smc;
#pragma unroll
    for (int i = 0; i < 4; i++) {
        const int r0 = wm + i * 16 + g;
        const int r1 = r0 + 8;
#pragma unroll
        for (int j = 0; j < 4; j++) {
            const int col = wn + j * 8 + 2 * t;
            *(float2*)&Cs[r0 * CS_STR + col] = make_float2(acc[i][j][0], acc[i][j][1]);
            *(float2*)&Cs[r1 * CS_STR + col] = make_float2(acc[i][j][2], acc[i][j][3]);
        }
    }
    __syncthreads();

    const float is2 = 0.70710678118654752f;
    for (int i = tid; i < 128 * 32; i += 256) {
        const int r  = i >> 5;
        const int c2 = (i & 31) * 2;
        float a0 = Cs[r * CS_STR + c2    ] + bias[n0m + c2    ];
        float a1 = Cs[r * CS_STR + c2 + 1] + bias[n0m + c2 + 1];
        float g0 = Cs[r * CS_STR + 64 + c2    ] + bias[FF + n0m + c2    ];
        float g1 = Cs[r * CS_STR + 64 + c2 + 1] + bias[FF + n0m + c2 + 1];
        float o0 = 0.5f * a0 * (1.0f + erff(a0 * is2)) * g0;
        float o1 = 0.5f * a1 * (1.0f + erff(a1 * is2)) * g1;
        *(__half2*)&Mout[(size_t)(m0 + r) * FF + n0m + c2] =
            __floats2half2_rn(o0, o1);
    }
}

// ---------------------------------------------------------------------------
// Flash attention, fp16 mma, 64-key tiles, ldmatrix fragment loads
// smem (halves): Q/P[64*72], K[2][64*72], VT[2][64*72] = 46080 B
// ---------------------------------------------------------------------------
#define FH_K    (64*72)                   // 4608 (Q/P region size)
#define FH_KSZ  (64*72)
#define FH_VT   (FH_K + 2*FH_KSZ)         // 13824
#define FH_VTSZ (64*72)
#define FH_TOT  (FH_VT + 2*FH_VTSZ)       // 23040 halves
#define FH_SMEM (FH_TOT * 2)              // 46080 bytes

__global__ void __launch_bounds__(128) flash_attn_f16_kernel(
    const __half* __restrict__ qh, const __half* __restrict__ kh,
    const __half* __restrict__ vth, __half* __restrict__ O)
{
    extern __shared__ __align__(16) char smc[];
    __half* smh = (__half*)smc;
    const int tid  = threadIdx.x;
    const int warp = tid >> 5;
    const int lane = tid & 31;
    const int g = lane >> 2;
    const int t = lane & 3;
    const int wq = warp * 16;

    const int qt = blockIdx.x, h = blockIdx.y, b = blockIdx.z;
    const int rowBase = b * SS + qt * 64;
    const int cq = h * DH;
    const uint32_t smb = smem_u32(smh);
    const __half* vbh = vth + (size_t)(b * HH + h) * DH * SS;

    // ---- load Q tile (64 x 64 halves, stride 72) ----
    for (int i = tid; i < 64 * 8; i += 128) {
        int r = i >> 3, ch = (i & 7) * 8;
        *(uint4*)&smh[r * 72 + ch] =
            *(const uint4*)&qh[(size_t)(rowBase + r) * DD + cq + ch];
    }

    // ---- K/VT prefetch: 64 keys per tile ----
    auto issue_tile = [&](int kt, int buf) {
        const __half* gK = kh + (size_t)(b * SS + kt * 64) * DD + cq;
        const uint32_t sK = smb + (FH_K + buf * FH_KSZ) * 2;
#pragma unroll
        for (int it = 0; it < 4; it++) {
            int i = tid + it * 128;          // 0..511
            int r = i >> 3, ch = (i & 7) * 8;
            cp_async16(sK + (r * 72 + ch) * 2, gK + (size_t)r * DD + ch);
        }
        const __half* gV = vbh + (size_t)kt * 64;
        const uint32_t sV = smb + (FH_VT + buf * FH_VTSZ) * 2;
#pragma unroll
        for (int it = 0; it < 4; it++) {
            int i = tid + it * 128;
            int r = i >> 3, ch = (i & 7) * 8;
            cp_async16(sV + (r * 72 + ch) * 2, gV + (size_t)r * SS + ch);
        }
        cp_commit();
    };
    issue_tile(0, 0);

    __syncthreads();

    const uint32_t aRow = (uint32_t)(lane & 15);
    const uint32_t aKh  = (uint32_t)((lane >> 4) << 3);
    const uint32_t bRow = (uint32_t)((lane & 7) + ((lane >> 4) << 3));
    const uint32_t bKh  = (uint32_t)(lane & 8);

    // ---- Q fragments (4 k16-steps) ----
    uint32_t qf[4][4];
#pragma unroll
    for (int ks = 0; ks < 4; ks++) {
        uint32_t addr = smb + (((uint32_t)wq + aRow) * 72 + ks * 16 + aKh) * 2;
        ldsm_x4(qf[ks][0], qf[ks][1], qf[ks][2], qf[ks][3], addr);
    }

    uint32_t* Pw = (uint32_t*)(smh) + warp * (16 * 36);   // 16 x 72 halves
    const uint32_t sPb = smb + (uint32_t)warp * (16 * 72) * 2;

    float m_i[2] = {-1e30f, -1e30f};
    float l_i[2] = {0.f, 0.f};
    float acc[8][4];
#pragma unroll
    for (int d = 0; d < 8; d++)
#pragma unroll
        for (int r = 0; r < 4; r++) acc[d][r] = 0.f;

    const int NT = SS / 64;   // 32
    for (int kt = 0; kt < NT; kt++) {
        const int cur = kt & 1;
        if (kt + 1 < NT) {
            issue_tile(kt + 1, 1 - cur);
            cp_wait<1>();
        } else {
            cp_wait<0>();
        }
        __syncthreads();

        const uint32_t sKb = smb + (FH_K  + cur * FH_KSZ)  * 2;
        const uint32_t sVb = smb + (FH_VT + cur * FH_VTSZ) * 2;

        // ---- S = Q K^T : 16 x 64 per warp ----
        float s4[8][4];
#pragma unroll
        for (int n = 0; n < 8; n++)
#pragma unroll
            for (int r = 0; r < 4; r++) s4[n][r] = 0.f;

#pragma unroll
        for (int ks = 0; ks < 4; ks++) {
            uint32_t kf[8][2];
#pragma unroll
            for (int jp = 0; jp < 4; jp++) {
                uint32_t addr = sKb + (((uint32_t)(jp * 16) + bRow) * 72 + ks * 16 + bKh) * 2;
                ldsm_x4(kf[2 * jp][0], kf[2 * jp][1],
                        kf[2 * jp + 1][0], kf[2 * jp + 1][1], addr);
            }
#pragma unroll
            for (int n = 0; n < 8; n++)
                mma_f16(s4[n][0], s4[n][1], s4[n][2], s4[n][3],
                        qf[ks][0], qf[ks][1], qf[ks][2], qf[ks][3],
                        kf[n][0], kf[n][1]);
        }

        // ---- online softmax (rows wq+g, wq+g+8) ----
        float mx0 = -1e30f, mx1 = -1e30f;
#pragma unroll
        for (int n = 0; n < 8; n++) {
            mx0 = fmaxf(mx0, fmaxf(s4[n][0], s4[n][1]));
            mx1 = fmaxf(mx1, fmaxf(s4[n][2], s4[n][3]));
        }
        mx0 = fmaxf(mx0, __shfl_xor_sync(0xffffffffu, mx0, 1));
        mx0 = fmaxf(mx0, __shfl_xor_sync(0xffffffffu, mx0, 2));
        mx1 = fmaxf(mx1, __shfl_xor_sync(0xffffffffu, mx1, 1));
        mx1 = fmaxf(mx1, __shfl_xor_sync(0xffffffffu, mx1, 2));

        float mn0 = fmaxf(m_i[0], mx0);
        float mn1 = fmaxf(m_i[1], mx1);
        float cr0 = __expf(m_i[0] - mn0);
        float cr1 = __expf(m_i[1] - mn1);

        float sum0 = 0.f, sum1 = 0.f;
#pragma unroll
        for (int n = 0; n < 8; n++) {
            s4[n][0] = __expf(s4[n][0] - mn0);
            s4[n][1] = __expf(s4[n][1] - mn0);
            s4[n][2] = __expf(s4[n][2] - mn1);
            s4[n][3] = __expf(s4[n][3] - mn1);
            sum0 += s4[n][0] + s4[n][1];
            sum1 += s4[n][2] + s4[n][3];
        }
        sum0 += __shfl_xor_sync(0xffffffffu, sum0, 1);
        sum0 += __shfl_xor_sync(0xffffffffu, sum0, 2);
        sum1 += __shfl_xor_sync(0xffffffffu, sum1, 1);
        sum1 += __shfl_xor_sync(0xffffffffu, sum1, 2);

        l_i[0] = l_i[0] * cr0 + sum0;
        l_i[1] = l_i[1] * cr1 + sum1;
        m_i[0] = mn0; m_i[1] = mn1;

#pragma unroll
        for (int d = 0; d < 8; d++) {
            acc[d][0] *= cr0; acc[d][1] *= cr0;
            acc[d][2] *= cr1; acc[d][3] *= cr1;
        }

        // ---- store P as fp16 (16 x 64, stride 72) ----
#pragma unroll
        for (int n = 0; n < 8; n++) {
            Pw[ g      * 36 + n * 4 + t] =
                h2_as_u32(__floats2half2_rn(s4[n][0], s4[n][1]));
            Pw[(g + 8) * 36 + n * 4 + t] =
                h2_as_u32(__floats2half2_rn(s4[n][2], s4[n][3]));
        }
        __syncwarp();

        // ---- acc += P @ V : 4 ksteps x 8 d-cols ----
#pragma unroll
        for (int ks = 0; ks < 4; ks++) {
            uint32_t pa[4];
            {
                uint32_t addr = sPb + (aRow * 72 + ks * 16 + aKh) * 2;
                ldsm_x4(pa[0], pa[1], pa[2], pa[3], addr);
            }
            uint32_t vf[8][2];
#pragma unroll
            for (int dp = 0; dp < 4; dp++) {
                uint32_t addr = sVb + (((uint32_t)(dp * 16) + bRow) * 72 + ks * 16 + bKh) * 2;
                ldsm_x4(vf[2 * dp][0], vf[2 * dp][1],
                        vf[2 * dp + 1][0], vf[2 * dp + 1][1], addr);
            }
#pragma unroll
            for (int d = 0; d < 8; d++)
                mma_f16(acc[d][0], acc[d][1], acc[d][2], acc[d][3],
                        pa[0], pa[1], pa[2], pa[3], vf[d][0], vf[d][1]);
        }
        __syncthreads();
    }

    const float inv0 = 1.0f / l_i[0];
    const float inv1 = 1.0f / l_i[1];
    const int r0 = rowBase + wq + g;
    const int r1 = r0 + 8;
#pragma unroll
    for (int d = 0; d < 8; d++) {
        const int col = cq + d * 8 + 2 * t;
        *(__half2*)&O[(size_t)r0 * DD + col] =
            __floats2half2_rn(acc[d][0] * inv0, acc[d][1] * inv0);
        *(__half2*)&O[(size_t)r1 * DD + col] =
            __floats2half2_rn(acc[d][2] * inv1, acc[d][3] * inv1);
    }
}

// ---------------------------------------------------------------------------
// Fused residual add + LayerNorm (+ optional fp16 copy)
// ---------------------------------------------------------------------------
__global__ void __launch_bounds__(256) add_ln_kernel(
    const float* __restrict__ A, const float* __restrict__ R,
    const float* __restrict__ g, const float* __restrict__ be,
    float* __restrict__ out, __half* __restrict__ out_h)
{
    __shared__ float red[8];
    const int row = blockIdx.x, tid = threadIdx.x;
    const int lane = tid & 31, wid = tid >> 5;

    float4 a = ((const float4*)(A + (size_t)row * DD))[tid];
    float4 r = ((const float4*)(R + (size_t)row * DD))[tid];
    float4 t = make_float4(a.x + r.x, a.y + r.y, a.z + r.z, a.w + r.w);

    float ssum = t.x + t.y + t.z + t.w;
#pragma unroll
    for (int o = 16; o; o >>= 1) ssum += __shfl_xor_sync(0xffffffffu, ssum, o);
    if (lane == 0) red[wid] = ssum;
    __syncthreads();
    float mean = (red[0] + red[1] + red[2] + red[3] +
                  red[4] + red[5] + red[6] + red[7]) * (1.0f / DD);
    __syncthreads();

    float4 d = make_float4(t.x - mean, t.y - mean, t.z - mean, t.w - mean);
    float sq = d.x * d.x + d.y * d.y + d.z * d.z + d.w * d.w;
#pragma unroll
    for (int o = 16; o; o >>= 1) sq += __shfl_xor_sync(0xffffffffu, sq, o);
    if (lane == 0) red[wid] = sq;
    __syncthreads();
    float var = (red[0] + red[1] + red[2] + red[3] +
                 red[4] + red[5] + red[6] + red[7]) * (1.0f / DD);
    float rs = rsqrtf(var + 1e-5f);

    float4 gv = ((const float4*)g)[tid];
    float4 bv = ((const float4*)be)[tid];
    float4 o4 = make_float4(d.x * rs * gv.x + bv.x,
                            d.y * rs * gv.y + bv.y,
                            d.z * rs * gv.z + bv.z,
                            d.w * rs * gv.w + bv.w);
    ((float4*)(out + (size_t)row * DD))[tid] = o4;
    if (out_h) {
        __half2* oh = (__half2*)(out_h + (size_t)row * DD);
        oh[2 * tid]     = __floats2half2_rn(o4.x, o4.y);
        oh[2 * tid + 1] = __floats2half2_rn(o4.z, o4.w);
    }
}

// ---------------------------------------------------------------------------
// kernel_launch
// ---------------------------------------------------------------------------
extern "C" void kernel_launch(void* const* d_in, const int* in_sizes, int n_in,
                              void* d_out, int out_size)
{
    const float* x      = (const float*)d_in[0];
    const int*   p      = (const int*)  d_in[1];
    const float* Wqkv   = (const float*)d_in[2];
    const float* bqkv   = (const float*)d_in[3];
    const float* Wo     = (const float*)d_in[4];
    const float* bo     = (const float*)d_in[5];
    const float* gattn  = (const float*)d_in[6];
    const float* battn  = (const float*)d_in[7];
    const float* W1     = (const float*)d_in[8];
    const float* b1     = (const float*)d_in[9];
    const float* W2     = (const float*)d_in[10];
    const float* b2     = (const float*)d_in[11];
    const float* gmlp   = (const float*)d_in[12];
    const float* bmlp   = (const float*)d_in[13];
    const float* freqs  = (const float*)d_in[14];
    float* out = (float*)d_out;

    float *proj, *hbuf, *m2;
    __half *xh, *wqkvh, *woh, *w1h, *w2h, *attnh, *hh, *mh;
    __half *qh, *kh, *vth;
    cudaGetSymbolAddress((void**)&proj, g_proj);
    cudaGetSymbolAddress((void**)&hbuf, g_hbuf);
    cudaGetSymbolAddress((void**)&m2,   g_m2);
    cudaGetSymbolAddress((void**)&xh,    g_xh);
    cudaGetSymbolAddress((void**)&wqkvh, g_wqkvh);
    cudaGetSymbolAddress((void**)&woh,   g_woh);
    cudaGetSymbolAddress((void**)&w1h,   g_w1h);
    cudaGetSymbolAddress((void**)&w2h,   g_w2h);
    cudaGetSymbolAddress((void**)&attnh, g_attnh);
    cudaGetSymbolAddress((void**)&hh,    g_hh);
    cudaGetSymbolAddress((void**)&mh,    g_mh);
    cudaGetSymbolAddress((void**)&qh,    g_qh);
    cudaGetSymbolAddress((void**)&kh,    g_kh);
    cudaGetSymbolAddress((void**)&vth,   g_vth);

    cudaFuncSetAttribute(flash_attn_f16_kernel,
                         cudaFuncAttributeMaxDynamicSharedMemorySize, FH_SMEM);
    cudaFuncSetAttribute(gemm_f16_nt_bias<float>,
                         cudaFuncAttributeMaxDynamicSharedMemorySize, GH_SMEM);
    cudaFuncSetAttribute(gemm_f16_nt_bias<__half>,
                         cudaFuncAttributeMaxDynamicSharedMemorySize, GH_SMEM);
    cudaFuncSetAttribute(gemm_qkv_rope,
                         cudaFuncAttributeMaxDynamicSharedMemorySize, QR_SMEM);
    cudaFuncSetAttribute(gemm_w1_gelu,
                         cudaFuncAttributeMaxDynamicSharedMemorySize, W1_SMEM);

    // 0) fp16 pre-conversion of GEMM inputs
    h_copy_kernel<<<(NTOK * DD / 4 + 255) / 256, 256>>>(x,    xh,    NTOK * DD / 4);
    h_copy_kernel<<<(D3 * DD / 4 + 255) / 256, 256>>>(Wqkv, wqkvh, D3 * DD / 4);
    h_copy_kernel<<<(DD * DD / 4 + 255) / 256, 256>>>(Wo,   woh,   DD * DD / 4);
    h_copy_kernel<<<(2 * FF * DD / 4 + 255) / 256, 256>>>(W1, w1h,  2 * FF * DD / 4);
    h_copy_kernel<<<(DD * FF / 4 + 255) / 256, 256>>>(W2,   w2h,   DD * FF / 4);

    // 1+2) QKV projection with fused RoPE / V-transpose epilogue
    gemm_qkv_rope<<<dim3(D3 / 128, NTOK / 128), 256, QR_SMEM>>>(
        xh, wqkvh, bqkv, p, freqs, qh, kh, vth, DD);

    // 3) Flash attention (fp16 TC, 64-key tiles), fp16 output
    flash_attn_f16_kernel<<<dim3(SS / 64, HH, BB), 128, FH_SMEM>>>(
        qh, kh, vth, attnh);

    // 4) Output projection
    gemm_f16_nt_bias<float><<<dim3(DD / 128, NTOK / 128), 256, GH_SMEM>>>(
        attnh, woh, bo, proj, NTOK, DD, DD);

    // 5) h = LN(proj + x); fp16 copy for W1 GEMM
    add_ln_kernel<<<NTOK, 256>>>(proj, x, gattn, battn, hbuf, hh);

    // 6+7) m = gelu(h@W1a^T + b1a) * (h@W1g^T + b1g) — fused
    gemm_w1_gelu<<<dim3(FF / 64, NTOK / 128), 256, W1_SMEM>>>(
        hh, w1h, b1, mh, NTOK, DD);

    // 8) m2 = m @ W2^T + b2
    gemm_f16_nt_bias<float><<<dim3(DD / 128, NTOK / 128), 256, GH_SMEM>>>(
        mh, w2h, b2, m2, NTOK, DD, FF);

    // 9) out = LN(m2 + h)
    add_ln_kernel<<<NTOK, 256>>>(m2, hbuf, gmlp, bmlp, out, nullptr);
}